// round 10
// baseline (speedup 1.0000x reference)
#include <cuda_runtime.h>

// FDTD wave update (round 9: 2 rows/block + shuffle halo + streaming hints):
//   u2 = 2*u1 - u0 + 0.25*lap5(u1) - 0.0025*(j2 - j0)
// Zero ("same") padding. Shapes: (16, 1, 1024, 1024) fp32. HBM-bound; at
// compulsory traffic already — this round targets DRAM-stream efficiency.

#define IMG_W 1024
#define IMG_H 1024
#define IMG_B 16
#define ROW_F4 (IMG_W / 4)   // 256 float4 per row

__global__ __launch_bounds__(256)
void fdtd_step_kernel(const float* __restrict__ u1,
                      const float* __restrict__ u0,
                      const float* __restrict__ j2,
                      const float* __restrict__ j0,
                      float* __restrict__ out)
{
    const int t    = threadIdx.x;          // 0..255 -> 4 contiguous x each
    const int lane = t & 31;
    const int rp   = blockIdx.x;           // row pair 0..511
    const int img  = blockIdx.y;           // 0..15
    const int r0   = rp << 1;              // even row of the pair

    const long base = (long)img * (IMG_H * IMG_W) + (long)r0 * IMG_W;
    const int  x0   = t << 2;

    const float4 zero = make_float4(0.f, 0.f, 0.f, 0.f);
    const float4* pU = reinterpret_cast<const float4*>(u1 + base) + t;

    // u1 rows r0-1, r0, r0+1, r0+2  (4 loads cover 2 output rows)
    const float4 um = (r0 > 0)            ? __ldg(pU - ROW_F4) : zero;
    const float4 c0 = __ldg(pU);
    const float4 c1 = __ldg(pU + ROW_F4);
    const float4 up2 = (r0 + 2 < IMG_H)   ? __ldg(pU + 2 * ROW_F4) : zero;

    // Use-once arrays: streaming loads (evict-first, keep u1 resident in L2)
    const float4 a0 = __ldcs(reinterpret_cast<const float4*>(u0 + base) + t);
    const float4 a1 = __ldcs(reinterpret_cast<const float4*>(u0 + base) + t + ROW_F4);
    const float4 p0 = __ldcs(reinterpret_cast<const float4*>(j2 + base) + t);
    const float4 p1 = __ldcs(reinterpret_cast<const float4*>(j2 + base) + t + ROW_F4);
    const float4 q0 = __ldcs(reinterpret_cast<const float4*>(j0 + base) + t);
    const float4 q1 = __ldcs(reinterpret_cast<const float4*>(j0 + base) + t + ROW_F4);

    // Horizontal halos via warp shuffle; only lane 0/31 touch memory (L1/L2 hit)
    const unsigned full = 0xFFFFFFFFu;
    float l0 = __shfl_up_sync(full, c0.w, 1);
    float l1 = __shfl_up_sync(full, c1.w, 1);
    float rt0 = __shfl_down_sync(full, c0.x, 1);
    float rt1 = __shfl_down_sync(full, c1.x, 1);
    if (lane == 0) {
        l0 = (t > 0) ? __ldg(u1 + base + x0 - 1)          : 0.f;
        l1 = (t > 0) ? __ldg(u1 + base + IMG_W + x0 - 1)  : 0.f;
    }
    if (lane == 31) {
        rt0 = (t < 255) ? __ldg(u1 + base + x0 + 4)         : 0.f;
        rt1 = (t < 255) ? __ldg(u1 + base + IMG_W + x0 + 4) : 0.f;
    }

    const float KL = 0.25f;    // DT^2*C^2/DX^2
    const float KJ = 0.0025f;  // DT/(2*EPS)

    // Row r0: up = um, center = c0, down = c1
    float4 o0;
    o0.x = 2.f*c0.x - a0.x + KL*(um.x + c1.x + l0   + c0.y - 4.f*c0.x) - KJ*(p0.x - q0.x);
    o0.y = 2.f*c0.y - a0.y + KL*(um.y + c1.y + c0.x + c0.z - 4.f*c0.y) - KJ*(p0.y - q0.y);
    o0.z = 2.f*c0.z - a0.z + KL*(um.z + c1.z + c0.y + c0.w - 4.f*c0.z) - KJ*(p0.z - q0.z);
    o0.w = 2.f*c0.w - a0.w + KL*(um.w + c1.w + c0.z + rt0  - 4.f*c0.w) - KJ*(p0.w - q0.w);

    // Row r0+1: up = c0, center = c1, down = up2
    float4 o1;
    o1.x = 2.f*c1.x - a1.x + KL*(c0.x + up2.x + l1   + c1.y - 4.f*c1.x) - KJ*(p1.x - q1.x);
    o1.y = 2.f*c1.y - a1.y + KL*(c0.y + up2.y + c1.x + c1.z - 4.f*c1.y) - KJ*(p1.y - q1.y);
    o1.z = 2.f*c1.z - a1.z + KL*(c0.z + up2.z + c1.y + c1.w - 4.f*c1.z) - KJ*(p1.z - q1.z);
    o1.w = 2.f*c1.w - a1.w + KL*(c0.w + up2.w + c1.z + rt1  - 4.f*c1.w) - KJ*(p1.w - q1.w);

    __stcs(reinterpret_cast<float4*>(out + base) + t,          o0);
    __stcs(reinterpret_cast<float4*>(out + base) + t + ROW_F4, o1);
}

extern "C" void kernel_launch(void* const* d_in, const int* in_sizes, int n_in,
                              void* d_out, int out_size)
{
    const float* u1 = (const float*)d_in[0];
    const float* u0 = (const float*)d_in[1];
    const float* j2 = (const float*)d_in[2];
    const float* j0 = (const float*)d_in[3];
    float* out = (float*)d_out;

    dim3 grid(IMG_H / 2, IMG_B);   // 512 row pairs x 16 images = 8192 blocks
    dim3 block(256);
    fdtd_step_kernel<<<grid, block>>>(u1, u0, j2, j0, out);
}

// round 11
// speedup vs baseline: 1.0056x; 1.0056x over previous
#include <cuda_runtime.h>

// FDTD wave update (round 9: 2 rows/block + shuffle halo + streaming hints):
//   u2 = 2*u1 - u0 + 0.25*lap5(u1) - 0.0025*(j2 - j0)
// Zero ("same") padding. Shapes: (16, 1, 1024, 1024) fp32. HBM-bound; at
// compulsory traffic already — this round targets DRAM-stream efficiency.

#define IMG_W 1024
#define IMG_H 1024
#define IMG_B 16
#define ROW_F4 (IMG_W / 4)   // 256 float4 per row

__global__ __launch_bounds__(256)
void fdtd_step_kernel(const float* __restrict__ u1,
                      const float* __restrict__ u0,
                      const float* __restrict__ j2,
                      const float* __restrict__ j0,
                      float* __restrict__ out)
{
    const int t    = threadIdx.x;          // 0..255 -> 4 contiguous x each
    const int lane = t & 31;
    const int rp   = blockIdx.x;           // row pair 0..511
    const int img  = blockIdx.y;           // 0..15
    const int r0   = rp << 1;              // even row of the pair

    const long base = (long)img * (IMG_H * IMG_W) + (long)r0 * IMG_W;
    const int  x0   = t << 2;

    const float4 zero = make_float4(0.f, 0.f, 0.f, 0.f);
    const float4* pU = reinterpret_cast<const float4*>(u1 + base) + t;

    // u1 rows r0-1, r0, r0+1, r0+2  (4 loads cover 2 output rows)
    const float4 um = (r0 > 0)            ? __ldg(pU - ROW_F4) : zero;
    const float4 c0 = __ldg(pU);
    const float4 c1 = __ldg(pU + ROW_F4);
    const float4 up2 = (r0 + 2 < IMG_H)   ? __ldg(pU + 2 * ROW_F4) : zero;

    // Use-once arrays: streaming loads (evict-first, keep u1 resident in L2)
    const float4 a0 = __ldcs(reinterpret_cast<const float4*>(u0 + base) + t);
    const float4 a1 = __ldcs(reinterpret_cast<const float4*>(u0 + base) + t + ROW_F4);
    const float4 p0 = __ldcs(reinterpret_cast<const float4*>(j2 + base) + t);
    const float4 p1 = __ldcs(reinterpret_cast<const float4*>(j2 + base) + t + ROW_F4);
    const float4 q0 = __ldcs(reinterpret_cast<const float4*>(j0 + base) + t);
    const float4 q1 = __ldcs(reinterpret_cast<const float4*>(j0 + base) + t + ROW_F4);

    // Horizontal halos via warp shuffle; only lane 0/31 touch memory (L1/L2 hit)
    const unsigned full = 0xFFFFFFFFu;
    float l0 = __shfl_up_sync(full, c0.w, 1);
    float l1 = __shfl_up_sync(full, c1.w, 1);
    float rt0 = __shfl_down_sync(full, c0.x, 1);
    float rt1 = __shfl_down_sync(full, c1.x, 1);
    if (lane == 0) {
        l0 = (t > 0) ? __ldg(u1 + base + x0 - 1)          : 0.f;
        l1 = (t > 0) ? __ldg(u1 + base + IMG_W + x0 - 1)  : 0.f;
    }
    if (lane == 31) {
        rt0 = (t < 255) ? __ldg(u1 + base + x0 + 4)         : 0.f;
        rt1 = (t < 255) ? __ldg(u1 + base + IMG_W + x0 + 4) : 0.f;
    }

    const float KL = 0.25f;    // DT^2*C^2/DX^2
    const float KJ = 0.0025f;  // DT/(2*EPS)

    // Row r0: up = um, center = c0, down = c1
    float4 o0;
    o0.x = 2.f*c0.x - a0.x + KL*(um.x + c1.x + l0   + c0.y - 4.f*c0.x) - KJ*(p0.x - q0.x);
    o0.y = 2.f*c0.y - a0.y + KL*(um.y + c1.y + c0.x + c0.z - 4.f*c0.y) - KJ*(p0.y - q0.y);
    o0.z = 2.f*c0.z - a0.z + KL*(um.z + c1.z + c0.y + c0.w - 4.f*c0.z) - KJ*(p0.z - q0.z);
    o0.w = 2.f*c0.w - a0.w + KL*(um.w + c1.w + c0.z + rt0  - 4.f*c0.w) - KJ*(p0.w - q0.w);

    // Row r0+1: up = c0, center = c1, down = up2
    float4 o1;
    o1.x = 2.f*c1.x - a1.x + KL*(c0.x + up2.x + l1   + c1.y - 4.f*c1.x) - KJ*(p1.x - q1.x);
    o1.y = 2.f*c1.y - a1.y + KL*(c0.y + up2.y + c1.x + c1.z - 4.f*c1.y) - KJ*(p1.y - q1.y);
    o1.z = 2.f*c1.z - a1.z + KL*(c0.z + up2.z + c1.y + c1.w - 4.f*c1.z) - KJ*(p1.z - q1.z);
    o1.w = 2.f*c1.w - a1.w + KL*(c0.w + up2.w + c1.z + rt1  - 4.f*c1.w) - KJ*(p1.w - q1.w);

    __stcs(reinterpret_cast<float4*>(out + base) + t,          o0);
    __stcs(reinterpret_cast<float4*>(out + base) + t + ROW_F4, o1);
}

extern "C" void kernel_launch(void* const* d_in, const int* in_sizes, int n_in,
                              void* d_out, int out_size)
{
    const float* u1 = (const float*)d_in[0];
    const float* u0 = (const float*)d_in[1];
    const float* j2 = (const float*)d_in[2];
    const float* j0 = (const float*)d_in[3];
    float* out = (float*)d_out;

    dim3 grid(IMG_H / 2, IMG_B);   // 512 row pairs x 16 images = 8192 blocks
    dim3 block(256);
    fdtd_step_kernel<<<grid, block>>>(u1, u0, j2, j0, out);
}